// round 14
// baseline (speedup 1.0000x reference)
#include <cuda_runtime.h>
#include <math.h>

#define ZDIM    4736      // 4*UNITS
#define LN10K   9.210340371976184f
#define NBLK    128
#define NTHR    256

// Device globals (no allocation allowed)
__device__ __align__(16) float g_KC[64 * 2 * 64];   // [l-1][h*64+k], l = 1..64
__device__ __align__(16) float g_VC[64 * 2 * 64];
__device__ __align__(16) float g_o[128 * 64];       // o row-major: [b][k]
__device__ unsigned g_bar1 = 0, g_bar2 = 0, g_done = 0;

__device__ __forceinline__ float sigd(float x) { return 1.0f / (1.0f + __expf(-x)); }

__device__ __forceinline__ float pe_val(int l, int i) {
    float e = (float)(2 * (i / 2)) * (1.0f / 64.0f);
    float invfreq = __expf(-e * LN10K);
    float ang = (float)l * invfreq;
    return (i & 1) ? cosf(ang) : sinf(ang);
}

// Packed dual-FMA: d = a*b + d on two f32 lanes (sm_100+).
__device__ __forceinline__ void fma2(unsigned long long& d,
                                     unsigned long long a, unsigned long long b) {
    asm("fma.rn.f32x2 %0, %1, %2, %0;" : "+l"(d) : "l"(a), "l"(b));
}
__device__ __forceinline__ float pairsum(unsigned long long v) {
    return __uint_as_float((unsigned)v) + __uint_as_float((unsigned)(v >> 32));
}

// Grid barrier: 128 co-resident blocks; nanosleep backoff (parked, no LSU
// pressure on the SMSP) + trip bound (never hangs even on a degraded part).
__device__ __forceinline__ void grid_bar(unsigned* ctr) {
    __syncthreads();
    if (threadIdx.x == 0) {
        __threadfence();
        atomicAdd(ctr, 1u);
        volatile unsigned* v = (volatile unsigned*)ctr;
        unsigned trips = 0;
        while (*v < (unsigned)NBLK && trips < 50000000u) { __nanosleep(32); trips++; }
        __threadfence();
    }
    __syncthreads();
}

// Dynamic shared layout (~89KB > 48KB static limit -> opt-in dynamic)
struct Sm {
    float  Wg[8][3][64];         // phase-C gate weights (6KB)
    float  Wo_s[128 * 64];       // Wo prefetch (32KB)
    float  VC_s[64 * 128];       // VC copy, filled during B1 (32KB)
    float4 cs4[256];             // colsum partials
    float  Bv[8][3];
    float  aug0[64], augl[64];
    float  pq[256], pk[256], pv[256], pa[256];
    float  q[128], k0[128], v0[128];
    float  logit[130], attn[130];
    float  ctx[128];
    float  opart[256];
    float  Hs[8][132];
};

// ---------------------------------------------------------------------------
// Single fused kernel. grid = 128 (block = batch row b; also produces half a
// KC/VC row: l = bid/2 + 1, K if bid even else V). block = 256 (8 warps).
// ---------------------------------------------------------------------------
__global__ void __launch_bounds__(NTHR) k_fused(
        const float* __restrict__ queries, const float* __restrict__ values,
        const float* __restrict__ Wi, const float* __restrict__ bi,
        const float* __restrict__ Wm, const float* __restrict__ bm,
        const float* __restrict__ Wq, const float* __restrict__ bq,
        const float* __restrict__ Wk, const float* __restrict__ bk,
        const float* __restrict__ Wv, const float* __restrict__ bv,
        const float* __restrict__ Wo, const float* __restrict__ bo,
        const float* __restrict__ Wx, const float* __restrict__ bl,
        float* __restrict__ out, float m) {
    extern __shared__ __align__(16) char smraw[];
    Sm* s = (Sm*)smraw;

    const int bid = blockIdx.x;
    const int t = threadIdx.x;
    const int j0 = bid * 8;
    const int grpoff[3] = {0, 2368, 3552};         // zi, zg, zo column groups
    const int lrow = (bid >> 1) + 1;

    // ---- A0: prefetch Wx tile (6/thread) + Wo (8 float4/thread); all
    //      independent loads, one overlapped epoch.
    #pragma unroll
    for (int r = 0; r < 6; r++) {
        int idx = r * NTHR + t;                    // 1536 elements
        int jj = idx & 7;
        int kg = idx >> 3;
        int g  = kg % 3;
        int k  = kg / 3;
        s->Wg[jj][g][k] = Wx[k * ZDIM + grpoff[g] + j0 + jj];
    }
    {
        const float4* wo4 = (const float4*)Wo;     // 2048 float4
        float4* wod = (float4*)s->Wo_s;
        #pragma unroll
        for (int r = 0; r < 8; r++) wod[r * NTHR + t] = wo4[r * NTHR + t];
    }
    if (t < 24) s->Bv[t & 7][t >> 3] = bl[grpoff[t >> 3] + j0 + (t & 7)];

    // ---- colsum(Wm): 16 independent float4 loads per thread (same epoch)
    float4 csacc;
    {
        const float4* wm4 = (const float4*)Wm;     // 4096 float4; col4 = t&15
        float4 acc = make_float4(0.f, 0.f, 0.f, 0.f);
        #pragma unroll
        for (int r = 0; r < 16; r++) {
            float4 v = wm4[r * NTHR + t];
            acc.x += v.x; acc.y += v.y; acc.z += v.z; acc.w += v.w;
        }
        csacc = acc;
    }

    // ---- A2: emb_in + PE[0] (t<64); x read directly from global
    if (t < 64) {
        float sum = bi[t];
        #pragma unroll
        for (int i = 0; i < 16; i++) sum += queries[bid * 16 + i] * Wi[i * 64 + t];
        #pragma unroll
        for (int i = 0; i < 16; i++)
            sum += values[(bid / 16) * 128 + 112 + i] * Wi[(16 + i) * 64 + t];
        s->aug0[t] = sum + ((t & 1) ? 1.0f : 0.0f);
    }
    s->cs4[t] = csacc;
    __syncthreads();   // aug0 + cs4 visible

    // ---- A3: q/k0/v0 matvec, 2-way d-split: col = t&127, half = t>>7
    {
        int col = t & 127, half = t >> 7;
        float aq = 0.f, ak = 0.f, av = 0.f;
        #pragma unroll
        for (int d = half * 32; d < half * 32 + 32; d++) {
            float a = s->aug0[d];
            aq += a * Wq[d * 128 + col];
            ak += a * Wk[d * 128 + col];
            av += a * Wv[d * 128 + col];
        }
        s->pq[t] = aq; s->pk[t] = ak; s->pv[t] = av;
    }
    __syncthreads();

    // combine q/k0/v0 (t<128); augl (t in [128,192))
    if (t < 128) {
        s->q[t]  = bq[t] + s->pq[t] + s->pq[t + 128];
        s->k0[t] = bk[t] + s->pk[t] + s->pk[t + 128];
        s->v0[t] = bv[t] + s->pv[t] + s->pv[t + 128];
    } else if (t < 192) {
        int d = t - 128;
        const float* csf = (const float*)s->cs4;
        float cs = 0.f;
        #pragma unroll
        for (int r = 0; r < 16; r++) cs += csf[((d >> 2) + 16 * r) * 4 + (d & 3)];
        s->augl[d] = m * cs + bm[d] + pe_val(lrow, d);
    }
    __syncthreads();

    // ---- A4: half a KC/VC row (even bid -> K, odd -> V), 2-way d-split.
    //      Partials into dedicated pa[] (no same-region write/read hazard).
    {
        const float* W = (bid & 1) ? Wv : Wk;
        int col = t & 127, half = t >> 7;
        float a = 0.f;
        #pragma unroll
        for (int d = half * 32; d < half * 32 + 32; d++)
            a += s->augl[d] * W[d * 128 + col];
        s->pa[t] = a;
    }
    __syncthreads();
    if (t < 128) {
        const float* bb = (bid & 1) ? bv : bk;
        float* dst      = (bid & 1) ? g_VC : g_KC;
        dst[(lrow - 1) * 128 + t] = bb[t] + s->pa[t] + s->pa[t + 128];
    }

    grid_bar(&g_bar1);   // KC/VC published

    // ---- B1: logits (t<130) || VC -> shared copy (t in [130,256)), 1 epoch
    if (t < 130) {
        int h = (t >= 65) ? 1 : 0;
        int l = t - 65 * h;
        const float* kp = (l == 0) ? &s->k0[h * 64] : &g_KC[(l - 1) * 128 + h * 64];
        float sum = 0.0f;
        #pragma unroll
        for (int d = 0; d < 64; d++) sum += s->q[h * 64 + d] * kp[d];
        s->logit[t] = sum * 0.125f;
    } else {
        const float4* src = (const float4*)g_VC;   // 2048 float4
        float4* dst = (float4*)s->VC_s;
        int base = t - 130;                        // 126 loader threads
        #pragma unroll
        for (int r = 0; r < 17; r++) {
            int idx = base + 126 * r;
            if (idx < 2048) dst[idx] = src[idx];
        }
    }
    __syncthreads();

    // ---- B2: softmax (warp 0 -> head 0, warp 1 -> head 1)
    {
        int w = t >> 5, lane = t & 31;
        if (w < 2) {
            int base = w * 65;
            float a0 = s->logit[base + lane];
            float a1 = s->logit[base + 32 + lane];
            float a2 = (lane == 0) ? s->logit[base + 64] : -1e30f;
            float mx = fmaxf(fmaxf(a0, a1), a2);
            #pragma unroll
            for (int off = 16; off > 0; off >>= 1)
                mx = fmaxf(mx, __shfl_xor_sync(0xffffffffu, mx, off));
            float e0 = __expf(a0 - mx);
            float e1 = __expf(a1 - mx);
            float e2 = (lane == 0) ? __expf(a2 - mx) : 0.0f;
            float sum = e0 + e1 + e2;
            #pragma unroll
            for (int off = 16; off > 0; off >>= 1)
                sum += __shfl_xor_sync(0xffffffffu, sum, off);
            float inv = 1.0f / sum;
            s->attn[base + lane] = e0 * inv;
            s->attn[base + 32 + lane] = e1 * inv;
            if (lane == 0) s->attn[base + 64] = e2 * inv;
        }
    }
    __syncthreads();

    // ---- B3: ctx from SHARED VC (no L2 epoch)
    if (t < 128) {
        int h = t >> 6;
        float sum = s->attn[h * 65] * s->v0[t];
        #pragma unroll
        for (int l = 1; l < 65; l++)
            sum += s->attn[h * 65 + l] * s->VC_s[(l - 1) * 128 + t];
        s->ctx[t] = sum;
    }
    __syncthreads();

    // ---- B4: o matvec from SHARED Wo (no L2 epoch), 4-way hk-split
    {
        int col = t & 63, qtr = t >> 6;
        float sum = 0.f;
        #pragma unroll
        for (int hk = 0; hk < 32; hk++)
            sum += s->ctx[qtr * 32 + hk] * s->Wo_s[(qtr * 32 + hk) * 64 + col];
        s->opart[t] = sum;
    }
    __syncthreads();
    if (t < 64)
        g_o[bid * 64 + t] = bo[t] + s->opart[t] + s->opart[t + 64]
                          + s->opart[t + 128] + s->opart[t + 192];

    grid_bar(&g_bar2);   // o published

    // ---- C: gate GEMM with packed f32x2 FMA. thread = (b = t&127, jsel = t>>7)
    {
        int b = t & 127, jsel = t >> 7;
        ulonglong2 o2[16];
        const ulonglong2* gp = (const ulonglong2*)(g_o + b * 64);
        #pragma unroll
        for (int i = 0; i < 16; i++) o2[i] = gp[i];

        #pragma unroll
        for (int jr = 0; jr < 4; jr++) {
            int jj = jsel * 4 + jr;
            unsigned long long zi2 = 0ull, zg2 = 0ull, zo2 = 0ull;
            const ulonglong2* wi2 = (const ulonglong2*)s->Wg[jj][0];
            const ulonglong2* wg2 = (const ulonglong2*)s->Wg[jj][1];
            const ulonglong2* wo2 = (const ulonglong2*)s->Wg[jj][2];
            #pragma unroll
            for (int k = 0; k < 16; k++) {
                ulonglong2 wa = wi2[k], wb = wg2[k], wc = wo2[k];
                ulonglong2 ov = o2[k];
                fma2(zi2, ov.x, wa.x); fma2(zi2, ov.y, wa.y);
                fma2(zg2, ov.x, wb.x); fma2(zg2, ov.y, wb.y);
                fma2(zo2, ov.x, wc.x); fma2(zo2, ov.y, wc.y);
            }
            float zi = pairsum(zi2) + s->Bv[jj][0];
            float zg = pairsum(zg2) + s->Bv[jj][1];
            float zo = pairsum(zo2) + s->Bv[jj][2];
            float c = sigd(zi) * tanhf(zg);
            s->Hs[jj][b] = sigd(zo) * tanhf(c);
        }
    }
    __syncthreads();

    // staged coalesced writes (1024 elements)
    #pragma unroll
    for (int r = 0; r < 4; r++) {
        int idx = r * NTHR + t;
        int jj = idx & 7, bb = idx >> 3;
        out[bb * 1024 + j0 + jj] = s->Hs[jj][bb];
    }

    // ---- Cleanup: last block resets barrier counters for the next replay
    __syncthreads();
    if (t == 0) {
        __threadfence();
        unsigned d = atomicAdd(&g_done, 1u);
        if (d == (unsigned)(NBLK - 1)) {
            g_bar1 = 0; g_bar2 = 0;
            __threadfence();
            g_done = 0;
        }
    }
}

// ---------------------------------------------------------------------------
// Host-side replica of the pot decay (input-independent).
static float sig_h(float x) { return 1.0f / (1.0f + expf(-x)); }
static float decay_h(float pc, float po) {
    float t0 = 0.07915332f * sig_h(100.0f * (0.0f - 0.5f)) * (1.5931877f - pc);
    float t1 = 1.0334609f  * sig_h(100.0f * (pc - 0.07879465f)) * (1.4378392f - pc);
    float t2 = 1.3365093f  * sig_h(100.0f * (po - 0.06618887f)) * (0.0f - pc);
    float t3 = 0.4505964f  * (0.0f - pc);
    return t0 + t1 + t2 + t3;
}
static float pot_scalar_h() {
    float p0 = 0.0f, p1 = 1.0f;
    const float PART = (float)(1.5573331 / 2.0);
    for (int s = 0; s < 7; s++)
        for (int d = 0; d < 2; d++) {
            float n0 = decay_h(p0, p1);
            float n1 = decay_h(p1, p0);
            p0 += n0 * PART;
            p1 += n1 * PART;
        }
    return p0;
}

extern "C" void kernel_launch(void* const* d_in, const int* in_sizes, int n_in,
                              void* d_out, int out_size) {
    const float* queries = (const float*)d_in[0];
    const float* values  = (const float*)d_in[1];
    const float* Wi      = (const float*)d_in[2];
    const float* bi      = (const float*)d_in[3];
    const float* Wm      = (const float*)d_in[4];
    const float* bm      = (const float*)d_in[5];
    const float* Wq      = (const float*)d_in[6];
    const float* bq      = (const float*)d_in[7];
    const float* Wk      = (const float*)d_in[8];
    const float* bk      = (const float*)d_in[9];
    const float* Wv      = (const float*)d_in[10];
    const float* bv      = (const float*)d_in[11];
    const float* Wo      = (const float*)d_in[12];
    const float* bo      = (const float*)d_in[13];
    const float* Wx      = (const float*)d_in[14];
    const float* bl      = (const float*)d_in[15];
    float* out = (float*)d_out;

    float m = pot_scalar_h();

    static int attr_set = 0;
    if (!attr_set) {
        cudaFuncSetAttribute(k_fused, cudaFuncAttributeMaxDynamicSharedMemorySize,
                             (int)sizeof(Sm));
        attr_set = 1;
    }

    k_fused<<<NBLK, NTHR, sizeof(Sm)>>>(queries, values, Wi, bi, Wm, bm,
                                        Wq, bq, Wk, bk, Wv, bv, Wo, bo,
                                        Wx, bl, out, m);
}

// round 15
// speedup vs baseline: 1.1190x; 1.1190x over previous
#include <cuda_runtime.h>
#include <math.h>

#define ZDIM    4736      // 4*UNITS
#define LN10K   9.210340371976184f
#define NBLK    128
#define NTHR    256

// Device globals (no allocation allowed)
__device__ __align__(16) float g_KC[64 * 2 * 64];   // [l-1][h*64+k], l = 1..64
__device__ __align__(16) float g_VC[64 * 2 * 64];
__device__ __align__(16) float g_o[128 * 64];       // o row-major: [b][k]
__device__ unsigned g_bar1 = 0, g_bar2 = 0, g_done = 0;

__device__ __forceinline__ float sigd(float x) { return 1.0f / (1.0f + __expf(-x)); }

__device__ __forceinline__ float pe_val(int l, int i) {
    float e = (float)(2 * (i / 2)) * (1.0f / 64.0f);
    float invfreq = __expf(-e * LN10K);
    float ang = (float)l * invfreq;
    return (i & 1) ? cosf(ang) : sinf(ang);
}

// Packed dual-FMA: d = a*b + d on two f32 lanes (sm_100+).
__device__ __forceinline__ void fma2(unsigned long long& d,
                                     unsigned long long a, unsigned long long b) {
    asm("fma.rn.f32x2 %0, %1, %2, %0;" : "+l"(d) : "l"(a), "l"(b));
}
__device__ __forceinline__ float pairsum(unsigned long long v) {
    return __uint_as_float((unsigned)v) + __uint_as_float((unsigned)(v >> 32));
}

// Grid barrier (R5-proven): 128 co-resident blocks; nanosleep backoff.
__device__ __forceinline__ void grid_bar(unsigned* ctr) {
    __syncthreads();
    if (threadIdx.x == 0) {
        __threadfence();
        atomicAdd(ctr, 1u);
        volatile unsigned* v = (volatile unsigned*)ctr;
        unsigned trips = 0;
        while (*v < (unsigned)NBLK && trips < 50000000u) { __nanosleep(32); trips++; }
        __threadfence();
    }
    __syncthreads();
}

// Phase-A scratch overlaid with phase-C o staging (disjoint lifetimes)
union ScratchU {
    struct {
        float4 cs4[256];            // colsum partials
        float  pq[256], pk[256], pv[256], pa[256];
    } a;
    float o_s[128 * 66];            // o staged [b][k], pad 66 (8B-aligned rows)
};

// ---------------------------------------------------------------------------
// Single fused kernel (R5 skeleton). grid = 128 (block = batch row b; also
// produces half a KC/VC row: l = bid/2 + 1, K if even, V if odd). block = 256.
// ---------------------------------------------------------------------------
__global__ void __launch_bounds__(NTHR) k_fused(
        const float* __restrict__ queries, const float* __restrict__ values,
        const float* __restrict__ Wi, const float* __restrict__ bi,
        const float* __restrict__ Wm, const float* __restrict__ bm,
        const float* __restrict__ Wq, const float* __restrict__ bq,
        const float* __restrict__ Wk, const float* __restrict__ bk,
        const float* __restrict__ Wv, const float* __restrict__ bv,
        const float* __restrict__ Wo, const float* __restrict__ bo,
        const float* __restrict__ Wx, const float* __restrict__ bl,
        float* __restrict__ out, float m) {
    __shared__ __align__(16) ScratchU u;
    __shared__ __align__(16) float Wg[8][3][64];   // phase-C gate weights
    __shared__ float Bv[8][3];
    __shared__ float aug0[64], augl[64];
    __shared__ float q[128], k0[128], v0[128];
    __shared__ float logit[130], attn[130];
    __shared__ float ctx[128];
    __shared__ float opart[256];
    __shared__ float Hs[8][130];

    const int bid = blockIdx.x;
    const int t = threadIdx.x;
    const int j0 = bid * 8;
    const int grpoff[3] = {0, 2368, 3552};         // zi, zg, zo column groups
    const int lrow = (bid >> 1) + 1;

    // ---- A0: prefetch phase-C Wx tile (one overlapped epoch with colsum)
    #pragma unroll
    for (int r = 0; r < 6; r++) {
        int idx = r * NTHR + t;                    // 1536 elements
        int jj = idx & 7;
        int kg = idx >> 3;
        int g  = kg % 3;
        int k  = kg / 3;
        Wg[jj][g][k] = Wx[k * ZDIM + grpoff[g] + j0 + jj];
    }
    if (t < 24) Bv[t & 7][t >> 3] = bl[grpoff[t >> 3] + j0 + (t & 7)];

    // ---- colsum(Wm): 16 independent float4 loads per thread (same epoch)
    float4 csacc;
    {
        const float4* wm4 = (const float4*)Wm;     // 4096 float4; col4 = t&15
        float4 acc = make_float4(0.f, 0.f, 0.f, 0.f);
        #pragma unroll
        for (int r = 0; r < 16; r++) {
            float4 v = wm4[r * NTHR + t];
            acc.x += v.x; acc.y += v.y; acc.z += v.z; acc.w += v.w;
        }
        csacc = acc;
    }

    // ---- A2: emb_in + PE[0] (t<64); x read directly from global
    if (t < 64) {
        float sum = bi[t];
        #pragma unroll
        for (int i = 0; i < 16; i++) sum += queries[bid * 16 + i] * Wi[i * 64 + t];
        #pragma unroll
        for (int i = 0; i < 16; i++)
            sum += values[(bid / 16) * 128 + 112 + i] * Wi[(16 + i) * 64 + t];
        aug0[t] = sum + ((t & 1) ? 1.0f : 0.0f);
    }
    u.a.cs4[t] = csacc;
    __syncthreads();   // aug0 + cs4 visible

    // ---- A3: q/k0/v0 matvec, 2-way d-split; augl on threads [128,192)
    {
        int col = t & 127, half = t >> 7;
        float aq = 0.f, ak = 0.f, av = 0.f;
        #pragma unroll
        for (int d = half * 32; d < half * 32 + 32; d++) {
            float a = aug0[d];
            aq += a * Wq[d * 128 + col];
            ak += a * Wk[d * 128 + col];
            av += a * Wv[d * 128 + col];
        }
        u.a.pq[t] = aq; u.a.pk[t] = ak; u.a.pv[t] = av;
    }
    __syncthreads();

    // combine q/k0/v0 (t<128); augl (t in [128,192))
    if (t < 128) {
        q[t]  = bq[t] + u.a.pq[t] + u.a.pq[t + 128];
        k0[t] = bk[t] + u.a.pk[t] + u.a.pk[t + 128];
        v0[t] = bv[t] + u.a.pv[t] + u.a.pv[t + 128];
    } else if (t < 192) {
        int d = t - 128;
        const float* csf = (const float*)u.a.cs4;
        float cs = 0.f;
        #pragma unroll
        for (int r = 0; r < 16; r++) cs += csf[((d >> 2) + 16 * r) * 4 + (d & 3)];
        augl[d] = m * cs + bm[d] + pe_val(lrow, d);
    }
    __syncthreads();

    // ---- A4: half a KC/VC row, 2-way d-split into DEDICATED pa[] (race-free)
    {
        const float* W = (bid & 1) ? Wv : Wk;
        int col = t & 127, half = t >> 7;
        float a = 0.f;
        #pragma unroll
        for (int d = half * 32; d < half * 32 + 32; d++)
            a += augl[d] * W[d * 128 + col];
        u.a.pa[t] = a;
    }
    __syncthreads();
    if (t < 128) {
        const float* bb = (bid & 1) ? bv : bk;
        float* dst      = (bid & 1) ? g_VC : g_KC;
        dst[(lrow - 1) * 128 + t] = bb[t] + u.a.pa[t] + u.a.pa[t + 128];
    }

    grid_bar(&g_bar1);   // KC/VC published

    // ---- B1: logits (2 heads x 65), one thread per (h,l)
    if (t < 130) {
        int h = (t >= 65) ? 1 : 0;
        int l = t - 65 * h;
        const float* kp = (l == 0) ? &k0[h * 64] : &g_KC[(l - 1) * 128 + h * 64];
        float sum = 0.0f;
        #pragma unroll
        for (int d = 0; d < 64; d++) sum += q[h * 64 + d] * kp[d];
        logit[t] = sum * 0.125f;
    }
    __syncthreads();

    // ---- B2: softmax (warp 0 -> head 0, warp 1 -> head 1)
    {
        int w = t >> 5, lane = t & 31;
        if (w < 2) {
            int base = w * 65;
            float a0 = logit[base + lane];
            float a1 = logit[base + 32 + lane];
            float a2 = (lane == 0) ? logit[base + 64] : -1e30f;
            float mx = fmaxf(fmaxf(a0, a1), a2);
            #pragma unroll
            for (int off = 16; off > 0; off >>= 1)
                mx = fmaxf(mx, __shfl_xor_sync(0xffffffffu, mx, off));
            float e0 = __expf(a0 - mx);
            float e1 = __expf(a1 - mx);
            float e2 = (lane == 0) ? __expf(a2 - mx) : 0.0f;
            float sum = e0 + e1 + e2;
            #pragma unroll
            for (int off = 16; off > 0; off >>= 1)
                sum += __shfl_xor_sync(0xffffffffu, sum, off);
            float inv = 1.0f / sum;
            attn[base + lane] = e0 * inv;
            attn[base + 32 + lane] = e1 * inv;
            if (lane == 0) attn[base + 64] = e2 * inv;
        }
    }
    __syncthreads();

    // ---- B3: ctx, full-depth from L2 (R5-proven)
    if (t < 128) {
        int h = t >> 6;
        float sum = attn[h * 65] * v0[t];
        #pragma unroll
        for (int l = 1; l < 65; l++)
            sum += attn[h * 65 + l] * g_VC[(l - 1) * 128 + t];
        ctx[t] = sum;
    }
    __syncthreads();

    // ---- B4: o matvec, 4-way hk-split from L2 (R5-proven)
    {
        int col = t & 63, qtr = t >> 6;
        float sum = 0.f;
        const float* Wp = Wo + (qtr * 32) * 64 + col;
        #pragma unroll
        for (int hk = 0; hk < 32; hk++)
            sum += ctx[qtr * 32 + hk] * Wp[hk * 64];
        opart[t] = sum;
    }
    __syncthreads();
    if (t < 64)
        g_o[bid * 64 + t] = bo[t] + opart[t] + opart[t + 64]
                          + opart[t + 128] + opart[t + 192];

    grid_bar(&g_bar2);   // o published

    // ---- C-stage: coalesced g_o -> padded shared (256 wf instead of 512)
    {
        const float* gof = (const float*)g_o;      // 8192 floats
        #pragma unroll
        for (int r = 0; r < 32; r++) {
            int idx = r * NTHR + t;
            u.o_s[(idx >> 6) * 66 + (idx & 63)] = gof[idx];
        }
    }
    __syncthreads();

    // ---- C: gate GEMM with packed f32x2 FMA. thread = (b = t&127, jsel = t>>7)
    {
        int b = t & 127, jsel = t >> 7;
        unsigned long long o2[32];
        #pragma unroll
        for (int k = 0; k < 32; k++)
            o2[k] = *(const unsigned long long*)&u.o_s[b * 66 + 2 * k];

        #pragma unroll
        for (int jr = 0; jr < 4; jr++) {
            int jj = jsel * 4 + jr;
            unsigned long long zi2 = 0ull, zg2 = 0ull, zo2 = 0ull;
            const unsigned long long* wi2 = (const unsigned long long*)Wg[jj][0];
            const unsigned long long* wg2 = (const unsigned long long*)Wg[jj][1];
            const unsigned long long* wo2 = (const unsigned long long*)Wg[jj][2];
            #pragma unroll
            for (int k = 0; k < 32; k++) {
                unsigned long long ov = o2[k];
                fma2(zi2, ov, wi2[k]);
                fma2(zg2, ov, wg2[k]);
                fma2(zo2, ov, wo2[k]);
            }
            float zi = pairsum(zi2) + Bv[jj][0];
            float zg = pairsum(zg2) + Bv[jj][1];
            float zo = pairsum(zo2) + Bv[jj][2];
            float c = sigd(zi) * tanhf(zg);
            Hs[jj][b] = sigd(zo) * tanhf(c);
        }
    }
    __syncthreads();

    // staged coalesced writes (1024 elements)
    #pragma unroll
    for (int r = 0; r < 4; r++) {
        int idx = r * NTHR + t;
        int jj = idx & 7, bb = idx >> 3;
        out[bb * 1024 + j0 + jj] = Hs[jj][bb];
    }

    // ---- Cleanup: last block resets barrier counters for the next replay
    __syncthreads();
    if (t == 0) {
        __threadfence();
        unsigned d = atomicAdd(&g_done, 1u);
        if (d == (unsigned)(NBLK - 1)) {
            g_bar1 = 0; g_bar2 = 0;
            __threadfence();
            g_done = 0;
        }
    }
}

// ---------------------------------------------------------------------------
// Host-side replica of the pot decay (input-independent).
static float sig_h(float x) { return 1.0f / (1.0f + expf(-x)); }
static float decay_h(float pc, float po) {
    float t0 = 0.07915332f * sig_h(100.0f * (0.0f - 0.5f)) * (1.5931877f - pc);
    float t1 = 1.0334609f  * sig_h(100.0f * (pc - 0.07879465f)) * (1.4378392f - pc);
    float t2 = 1.3365093f  * sig_h(100.0f * (po - 0.06618887f)) * (0.0f - pc);
    float t3 = 0.4505964f  * (0.0f - pc);
    return t0 + t1 + t2 + t3;
}
static float pot_scalar_h() {
    float p0 = 0.0f, p1 = 1.0f;
    const float PART = (float)(1.5573331 / 2.0);
    for (int s = 0; s < 7; s++)
        for (int d = 0; d < 2; d++) {
            float n0 = decay_h(p0, p1);
            float n1 = decay_h(p1, p0);
            p0 += n0 * PART;
            p1 += n1 * PART;
        }
    return p0;
}

extern "C" void kernel_launch(void* const* d_in, const int* in_sizes, int n_in,
                              void* d_out, int out_size) {
    const float* queries = (const float*)d_in[0];
    const float* values  = (const float*)d_in[1];
    const float* Wi      = (const float*)d_in[2];
    const float* bi      = (const float*)d_in[3];
    const float* Wm      = (const float*)d_in[4];
    const float* bm      = (const float*)d_in[5];
    const float* Wq      = (const float*)d_in[6];
    const float* bq      = (const float*)d_in[7];
    const float* Wk      = (const float*)d_in[8];
    const float* bk      = (const float*)d_in[9];
    const float* Wv      = (const float*)d_in[10];
    const float* bv      = (const float*)d_in[11];
    const float* Wo      = (const float*)d_in[12];
    const float* bo      = (const float*)d_in[13];
    const float* Wx      = (const float*)d_in[14];
    const float* bl      = (const float*)d_in[15];
    float* out = (float*)d_out;

    float m = pot_scalar_h();

    k_fused<<<NBLK, NTHR>>>(queries, values, Wi, bi, Wm, bm, Wq, bq, Wk, bk,
                            Wv, bv, Wo, bo, Wx, bl, out, m);
}